// round 16
// baseline (speedup 1.0000x reference)
#include <cuda_runtime.h>

#define NEGV (-1e30f)

__device__ __forceinline__ float4 fmax4(float4 a, float4 b) {
    a.x = fmaxf(a.x, b.x);
    a.y = fmaxf(a.y, b.y);
    a.z = fmaxf(a.z, b.z);
    a.w = fmaxf(a.w, b.w);
    return a;
}

// One block (64 threads = 2 warps) per (token, side):
//   warp 0: d[  0:128), warp 1: d[128:256)
//
// PHASED LAUNCH ORDER: tokens are mapped to blocks in 4 phases by l-range
// (l in [0,128) for all batches first, ..., [384,512) last). P(token active)
// = (512-l)/512, so heavy blocks run in the full-width early waves and the
// tail waves are dominated by instant-exit masked blocks -> the straggler
// tail collapses. Within a phase consecutive bids share a batch, preserving
// per-SM L1 locality on the gathered rows.
//
// launch_bounds(64, 28): 36-reg budget -> 56 warps/SM with ~6 gather
// LDG.128 in flight per warp under unroll 8 (midpoint of the regs/warps
// surface between the 32r/64w and 40r/48w cells).
__global__ __launch_bounds__(64, 28) void path_max_kernel(
    const float* __restrict__ inputs,   // [B,L,D] f32, D=256
    const int*   __restrict__ lpaths,   // [B,L,P]
    const int*   __restrict__ rpaths,   // [B,L,P]
    const int*   __restrict__ llens,    // [B,L]
    const int*   __restrict__ rlens,    // [B,L]
    const int*   __restrict__ slens,    // [B]
    float*       __restrict__ out,      // [B,L,2D]
    int B)
{
    constexpr int L = 512, P = 32;

    const int side = blockIdx.x & 1;     // 0 = left, 1 = right
    const int tbid = blockIdx.x >> 1;    // phased token id

    // 4-phase decode: phase = tbid / (B*128); within a phase, batch-major
    // runs of 128 consecutive l values.
    const int per_phase = B << 7;        // B * 128
    const int phase = tbid / per_phase;
    const int r     = tbid - phase * per_phase;
    const int b     = r >> 7;
    const int l     = (phase << 7) + (r & 127);
    const int token = b * L + l;

    const int half  = threadIdx.x >> 5;  // 0 = d[0:128), 1 = d[128:256)
    const int lane  = threadIdx.x & 31;

    // Token row has 512 floats = 128 float4; this warp owns 32 of them.
    float4* o4 = reinterpret_cast<float4*>(out)
               + (size_t)token * 128 + side * 64 + half * 32 + lane;

    if (l >= __ldg(&slens[b])) {
        *o4 = make_float4(0.f, 0.f, 0.f, 0.f);
        return;
    }

    const int* __restrict__ paths = side ? rpaths : lpaths;
    const int len = side ? __ldg(&rlens[token]) : __ldg(&llens[token]);
    const int my  = __ldg(&paths[(size_t)token * P + lane]);

    // Each row of inputs[b] is 64 float4; this warp reads float4 column
    // (half*32 + lane) of each gathered row -> coalesced 512B per LDG.128.
    const float4* __restrict__ base =
        reinterpret_cast<const float4*>(inputs)
        + (size_t)b * L * 64 + half * 32 + lane;

    float4 m0 = make_float4(NEGV, NEGV, NEGV, NEGV);
    float4 m1 = m0;

    int idx = __shfl_sync(0xffffffffu, my, 0);
    #pragma unroll 8
    for (int p = 0; p < len; ++p) {
        const float4 v = __ldg(base + (size_t)idx * 64);
        idx = __shfl_sync(0xffffffffu, my, (p + 1) & 31);  // independent of v
        if (p & 1) m1 = fmax4(m1, v);
        else       m0 = fmax4(m0, v);
    }

    *o4 = fmax4(m0, m1);
}

extern "C" void kernel_launch(void* const* d_in, const int* in_sizes, int n_in,
                              void* d_out, int out_size) {
    const float* inputs = (const float*)d_in[0];
    const int*   lpaths = (const int*)d_in[1];
    const int*   rpaths = (const int*)d_in[2];
    const int*   llens  = (const int*)d_in[3];
    const int*   rlens  = (const int*)d_in[4];
    const int*   slens  = (const int*)d_in[5];

    const int B = in_sizes[5];          // sent_lens has B elements
    const int blocks = B * 512 * 2;     // one block per (token, side)

    path_max_kernel<<<blocks, 64>>>(inputs, lpaths, rpaths,
                                    llens, rlens, slens,
                                    (float*)d_out, B);
}

// round 17
// speedup vs baseline: 1.2370x; 1.2370x over previous
#include <cuda_runtime.h>

#define NEGV (-1e30f)

__device__ __forceinline__ float4 fmax4(float4 a, float4 b) {
    a.x = fmaxf(a.x, b.x);
    a.y = fmaxf(a.y, b.y);
    a.z = fmaxf(a.z, b.z);
    a.w = fmaxf(a.w, b.w);
    return a;
}

// Best-measured configuration (R14) + max-L1 carveout hint.
// One block (64 threads = 2 warps) per (token, side):
//   warp 0: d[  0:128)
//   warp 1: d[128:256)
// launch_bounds(64, 24): 42-reg budget (allocates 40) -> ~6-8 independent
// gather LDG.128 in flight per warp under unroll 8, 48 warps/SM theoretical.
// Batch-contiguous block order keeps a resident wave inside ~2 batches of
// input (~1.2MB) for L1 locality — reorderings that widen this footprint
// (R10 persistent stride, R16 phased) measurably regress.
// Lane p holds paths[token][p] (P == 32); index broadcast is a shfl on
// register state only, so unrolled loads are mutually independent.
__global__ __launch_bounds__(64, 24) void path_max_kernel(
    const float* __restrict__ inputs,   // [B,L,D] f32, D=256
    const int*   __restrict__ lpaths,   // [B,L,P]
    const int*   __restrict__ rpaths,   // [B,L,P]
    const int*   __restrict__ llens,    // [B,L]
    const int*   __restrict__ rlens,    // [B,L]
    const int*   __restrict__ slens,    // [B]
    float*       __restrict__ out)      // [B,L,2D]
{
    constexpr int L = 512, P = 32;

    const int token = blockIdx.x >> 1;
    const int side  = blockIdx.x & 1;    // 0 = left, 1 = right
    const int half  = threadIdx.x >> 5;  // 0 = d[0:128), 1 = d[128:256)
    const int lane  = threadIdx.x & 31;
    const int b     = token >> 9;        // token / L
    const int l     = token & (L - 1);   // token % L

    // Token row has 512 floats = 128 float4; this warp owns 32 of them.
    float4* o4 = reinterpret_cast<float4*>(out)
               + (size_t)token * 128 + side * 64 + half * 32 + lane;

    if (l >= __ldg(&slens[b])) {
        *o4 = make_float4(0.f, 0.f, 0.f, 0.f);
        return;
    }

    const int* __restrict__ paths = side ? rpaths : lpaths;
    const int len = side ? __ldg(&rlens[token]) : __ldg(&llens[token]);
    const int my  = __ldg(&paths[(size_t)token * P + lane]);

    // Each row of inputs[b] is 64 float4; this warp reads float4 column
    // (half*32 + lane) of each gathered row -> coalesced 512B per LDG.128.
    const float4* __restrict__ base =
        reinterpret_cast<const float4*>(inputs)
        + (size_t)b * L * 64 + half * 32 + lane;

    float4 m0 = make_float4(NEGV, NEGV, NEGV, NEGV);
    float4 m1 = m0;

    int idx = __shfl_sync(0xffffffffu, my, 0);
    #pragma unroll 8
    for (int p = 0; p < len; ++p) {
        const float4 v = __ldg(base + (size_t)idx * 64);
        idx = __shfl_sync(0xffffffffu, my, (p + 1) & 31);  // independent of v
        if (p & 1) m1 = fmax4(m1, v);
        else       m0 = fmax4(m0, v);
    }

    *o4 = fmax4(m0, m1);
}

extern "C" void kernel_launch(void* const* d_in, const int* in_sizes, int n_in,
                              void* d_out, int out_size) {
    const float* inputs = (const float*)d_in[0];
    const int*   lpaths = (const int*)d_in[1];
    const int*   rpaths = (const int*)d_in[2];
    const int*   llens  = (const int*)d_in[3];
    const int*   rlens  = (const int*)d_in[4];
    const int*   slens  = (const int*)d_in[5];

    const int B = in_sizes[5];          // sent_lens has B elements
    const int blocks = B * 512 * 2;     // one block per (token, side)

    // Kernel uses no shared memory: ask for the maximum L1D carveout so the
    // ~1.2MB resident gather working set gets every cache way available.
    static bool attr_set = false;
    if (!attr_set) {
        cudaFuncSetAttribute(path_max_kernel,
                             cudaFuncAttributePreferredSharedMemoryCarveout,
                             0 /* 0% shared -> max L1 */);
        attr_set = true;
    }

    path_max_kernel<<<blocks, 64>>>(inputs, lpaths, rpaths,
                                    llens, rlens, slens,
                                    (float*)d_out);
}